// round 15
// baseline (speedup 1.0000x reference)
#include <cuda_runtime.h>
#include <cuda_bf16.h>
#include <math.h>
#include <stdint.h>

// ---------------- problem constants ----------------
#define Tt   40
#define Ll   91
#define Cc   512
#define BQn  14400
#define BTn  640
#define MPAD 14592            // 57 * 256

// quantization scales (power of two: exact)
#define SA   16.0f
#define SB   512.0f
#define CLS_SCALE (2.0f / (SA * SB))

// ---------------- GEMM tiling (fp8: 1 byte/elt) ----------------
#define BM 256                // 8 pairs x 32 rows
#define BN 64
#define BKB 128               // K-bytes per chunk
#define NCH 4                 // 512 / 128
#define A_OFF 32768           // after resident B (4 x 8KB chunks)
#define A_PAIR_BYTES 8192     // 2 stages x 32 rows x 128B
#define TBOX_OFF (A_OFF + 8 * A_PAIR_BYTES)   // 98304
#define DYNSMEM (TBOX_OFF + BN * 8 * 4)       // 100352

#define FEAT_BLOCKS 3600      // BQn*Cc/8/256

// ---------------- scratch (zero-initialized device globals) ----------------
__device__ uint8_t g_A[(size_t)MPAD * Cc];   // fp8 e4m3 focal features * SA (pad rows zero)
__device__ uint8_t g_B[(size_t)BTn * Cc];    // fp8 e4m3 normalized lm * SB
__device__ float   g_tbox[BTn * 8];          // cx,cy,w,h,x0,y0,x1,y1

// ---------------- helpers ----------------
__device__ __forceinline__ uint32_t cvta_s(const void* p) {
    uint32_t a;
    asm("{ .reg .u64 t; cvta.to.shared.u64 t, %1; cvt.u32.u64 %0, t; }"
        : "=r"(a) : "l"(p));
    return a;
}

#define CP16(dst, src) asm volatile("cp.async.cg.shared.global [%0], [%1], 16;" :: "r"(dst), "l"(src))
#define CPCOMMIT()     asm volatile("cp.async.commit_group;")
#define CPWAIT(n)      asm volatile("cp.async.wait_group %0;" :: "n"(n))
#define PAIR_BAR(id)   asm volatile("bar.sync %0, 64;" :: "r"(id) : "memory")

__device__ __forceinline__ void ldsm4(uint32_t& r0, uint32_t& r1, uint32_t& r2,
                                      uint32_t& r3, uint32_t addr) {
    asm volatile("ldmatrix.sync.aligned.m8n8.x4.shared.b16 {%0,%1,%2,%3}, [%4];"
                 : "=r"(r0), "=r"(r1), "=r"(r2), "=r"(r3) : "r"(addr));
}

__device__ __forceinline__ void mma_fp8(float* d, const uint32_t* a,
                                        const uint32_t* b) {
    asm volatile(
        "mma.sync.aligned.m16n8k32.row.col.f32.e4m3.e4m3.f32 "
        "{%0,%1,%2,%3}, {%4,%5,%6,%7}, {%8,%9}, {%0,%1,%2,%3};"
        : "+f"(d[0]), "+f"(d[1]), "+f"(d[2]), "+f"(d[3])
        : "r"(a[0]), "r"(a[1]), "r"(a[2]), "r"(a[3]), "r"(b[0]), "r"(b[1]));
}

__device__ __forceinline__ uint16_t f2_to_e4m3x2(float lo, float hi) {
    uint16_t r;
    asm("cvt.rn.satfinite.e4m3x2.f32 %0, %1, %2;" : "=h"(r) : "f"(hi), "f"(lo));
    return r;
}

// swizzled byte offset: 128B rows, 8 chunks of 16B, 8-way XOR
__device__ __forceinline__ uint32_t swoff(int r, int c) {
    return (uint32_t)(r * 128 + ((c ^ (r & 7)) << 4));
}

// ---------------- focal feature: 3-MUFU softplus form ----------------
__device__ __forceinline__ float focal_feat(float x) {
    float e = __expf(-x);
    float t = __logf(1.f + e);
    float p = __fdividef(1.f, 1.f + e);
    float q = 1.f - p;
    return 0.25f * q * q * t - 0.75f * p * p * (x + t);
}

// ---------------- kernel 1: fused prep (features + targets) ----------------
__global__ void prep_kernel(const float* __restrict__ logits,
                            const float* __restrict__ label_maps,
                            const float* __restrict__ boxes,
                            const int*   __restrict__ class_labels) {
    int bid = blockIdx.x;
    int tid = threadIdx.x;
    if (bid < FEAT_BLOCKS) {
        int base = (bid * 256 + tid) * 8;
        float4 x0 = *(const float4*)(logits + base);
        float4 x1 = *(const float4*)(logits + base + 4);
        float f[8] = { x0.x, x0.y, x0.z, x0.w, x1.x, x1.y, x1.z, x1.w };
        uint16_t w[4];
        #pragma unroll
        for (int i = 0; i < 4; i++)
            w[i] = f2_to_e4m3x2(focal_feat(f[2 * i]) * SA,
                                focal_feat(f[2 * i + 1]) * SA);
        uint2 pk;
        pk.x = (uint32_t)w[0] | ((uint32_t)w[1] << 16);
        pk.y = (uint32_t)w[2] | ((uint32_t)w[3] << 16);
        *(uint2*)(g_A + base) = pk;
    } else {
        int j = bid - FEAT_BLOCKS;          // 0..639
        int b = j / Tt;
        int cls = class_labels[j];
        const float* row = label_maps + ((size_t)b * Ll + cls) * Cc;
        float2 v = *(const float2*)(row + tid * 2);
        float s = v.x + v.y;
        #pragma unroll
        for (int o = 16; o; o >>= 1) s += __shfl_xor_sync(0xffffffffu, s, o);
        __shared__ float red[8];
        if ((tid & 31) == 0) red[tid >> 5] = s;
        __syncthreads();
        float inv = SB / (red[0] + red[1] + red[2] + red[3] +
                          red[4] + red[5] + red[6] + red[7]);
        *(uint16_t*)(g_B + (size_t)j * Cc + tid * 2) =
            f2_to_e4m3x2(v.x * inv, v.y * inv);
        if (tid == 0) {
            float cx = boxes[j * 4 + 0], cy = boxes[j * 4 + 1];
            float w  = boxes[j * 4 + 2], h  = boxes[j * 4 + 3];
            float* o = g_tbox + j * 8;
            o[0] = cx; o[1] = cy; o[2] = w; o[3] = h;
            o[4] = cx - 0.5f * w; o[5] = cy - 0.5f * h;
            o[6] = cx + 0.5f * w; o[7] = cy + 0.5f * h;
        }
    }
}

// ---------------- kernel 2: fp8 GEMM + fused cost epilogue, 512 threads ----------------
extern __shared__ char dynsmem[];

__global__ __launch_bounds__(512, 2) void cost_kernel(
    const float* __restrict__ pred_boxes,
    float* __restrict__ outp) {

    const int tid = threadIdx.x;
    const int wid = tid >> 5;
    const int lane = tid & 31;
    const int pair = wid & 7;        // pair owns A rows [pair*32, pair*32+32)
    const int wn = wid >> 3;         // 0/1: B column half
    const int l64 = (wn << 5) | lane;
    const int m0 = blockIdx.y * BM;
    const int n0 = blockIdx.x * BN;

    uint32_t smem = cvta_s(dynsmem);
    const uint32_t a_base = smem + A_OFF + pair * A_PAIR_BYTES;
    float* s_tbox = (float*)(dynsmem + TBOX_OFF);

    // stage target boxes (128 float4s)
    for (int i = tid; i < BN * 2; i += 512)
        ((float4*)s_tbox)[i] = *(const float4*)(g_tbox + (size_t)n0 * 8 + i * 4);

    // ---- prologue loads ----
    // B: whole 64x512 tile as 4 chunks of 64x128B = 2048 granules
    {
        #pragma unroll
        for (int i = 0; i < 4; i++) {
            int idx = tid + i * 512;          // 0..2047
            int ch = idx >> 9;
            int w9 = idx & 511;
            int r = w9 >> 3, c = w9 & 7;
            CP16(smem + ch * 8192 + swoff(r, c),
                 g_B + (size_t)(n0 + r) * Cc + ch * BKB + c * 16);
        }
        CPCOMMIT();
    }
    auto issueA = [&](int ch) {
        uint32_t st = a_base + (ch & 1) * 4096;
        const uint8_t* Ag = g_A + (size_t)(m0 + pair * 32) * Cc + ch * BKB;
        #pragma unroll
        for (int i = 0; i < 4; i++) {
            int idx = l64 + i * 64;
            int r = idx >> 3, c = idx & 7;
            CP16(st + swoff(r, c), Ag + (size_t)r * Cc + c * 16);
        }
        CPCOMMIT();
    };
    issueA(0); issueA(1);

    CPWAIT(2);             // B complete
    __syncthreads();       // B + tbox visible CTA-wide

    // ldmatrix constants (R8-proven)
    const int ar = lane & 15;
    const int ac = lane >> 4;
    const int axr = ar & 7;
    const int br = wn * 32 + ((lane >> 4) << 3) + (lane & 7);
    const int bc = (lane >> 3) & 1;
    const int bxr = br & 7;

    float acc[2][4][4];
    #pragma unroll
    for (int i = 0; i < 2; i++)
        #pragma unroll
        for (int j = 0; j < 4; j++)
            #pragma unroll
            for (int e = 0; e < 4; e++) acc[i][j][e] = 0.f;

    #pragma unroll
    for (int ch = 0; ch < NCH; ch++) {
        if (ch < NCH - 1) CPWAIT(1); else CPWAIT(0);
        PAIR_BAR(pair + 1);                     // pair's A(ch) visible

        uint32_t ast = a_base + (ch & 1) * 4096 + (uint32_t)ar * 128;
        uint32_t bst = smem + ch * 8192 + (uint32_t)br * 128;
        #pragma unroll
        for (int ks = 0; ks < 4; ks++) {
            uint32_t a[2][4], b[4][2];
            uint32_t ako = (uint32_t)(((ks * 2 + ac) ^ axr) << 4);
            uint32_t bko = (uint32_t)(((ks * 2 + bc) ^ bxr) << 4);
            ldsm4(a[0][0], a[0][1], a[0][2], a[0][3], ast + ako);
            ldsm4(a[1][0], a[1][1], a[1][2], a[1][3], ast + 2048 + ako);
            ldsm4(b[0][0], b[0][1], b[1][0], b[1][1], bst + bko);
            ldsm4(b[2][0], b[2][1], b[3][0], b[3][1], bst + 2048 + bko);
            #pragma unroll
            for (int mt = 0; mt < 2; mt++)
                #pragma unroll
                for (int nt = 0; nt < 4; nt++)
                    mma_fp8(acc[mt][nt], a[mt], b[nt]);
        }

        if (ch + 2 < NCH) {
            PAIR_BAR(pair + 1);                 // both warps done reading stage
            issueA(ch + 2);
        }
    }

    // ---------------- fused epilogue ----------------
    const int rbase = m0 + pair * 32 + (lane >> 2);
    const int cbase = wn * 32 + ((lane & 3) << 1);

    #pragma unroll
    for (int nt = 0; nt < 4; nt++) {
        int nl = cbase + nt * 8;
        float4 tc0 = *(const float4*)(s_tbox + nl * 8);
        float4 tk0 = *(const float4*)(s_tbox + nl * 8 + 4);
        float4 tc1 = *(const float4*)(s_tbox + (nl + 1) * 8);
        float4 tk1 = *(const float4*)(s_tbox + (nl + 1) * 8 + 4);
        float ta0 = tc0.z * tc0.w;              // target area = w*h
        float ta1 = tc1.z * tc1.w;

        #pragma unroll
        for (int mt = 0; mt < 2; mt++) {
            #pragma unroll
            for (int half = 0; half < 2; half++) {
                int m = rbase + mt * 16 + half * 8;
                if (m >= BQn) continue;
                float4 q = *(const float4*)(pred_boxes + (size_t)m * 4);
                float qx0 = q.x - 0.5f * q.z, qy0 = q.y - 0.5f * q.w;
                float qx1 = q.x + 0.5f * q.z, qy1 = q.y + 0.5f * q.w;
                float qarea = q.z * q.w;

                float r2[2];
                #pragma unroll
                for (int u = 0; u < 2; u++) {
                    float4 tc = u ? tc1 : tc0;
                    float4 tk = u ? tk1 : tk0;
                    float tarea = u ? ta1 : ta0;
                    float l1 = fabsf(q.x - tc.x) + fabsf(q.y - tc.y) +
                               fabsf(q.z - tc.z) + fabsf(q.w - tc.w);
                    float ltx = fmaxf(qx0, tk.x), lty = fmaxf(qy0, tk.y);
                    float rbx = fminf(qx1, tk.z), rby = fminf(qy1, tk.w);
                    float iwu = rbx - ltx, ihu = rby - lty;     // signed widths
                    float iw = fmaxf(iwu, 0.f), ih = fmaxf(ihu, 0.f);
                    float inter = iw * ih;
                    float uni = qarea + tarea - inter;
                    // enclosing box via width identity: no min/max needed
                    float ew = q.z + tc.z - iwu;                // wa + wb - signed overlap
                    float eh = q.w + tc.w - ihu;
                    float areaE = ew * eh;
                    float num = inter * areaE - uni * areaE + uni * uni;
                    float giou = __fdividef(num, uni * areaE);
                    float cls = acc[mt][nt][half * 2 + u];
                    r2[u] = 5.0f * l1 + CLS_SCALE * cls - 2.0f * giou;
                }
                *(float2*)(outp + (size_t)m * BTn + n0 + nl) = make_float2(r2[0], r2[1]);
            }
        }
    }
}

// ---------------- launcher ----------------
extern "C" void kernel_launch(void* const* d_in, const int* in_sizes, int n_in,
                              void* d_out, int out_size) {
    const float* logits       = (const float*)d_in[0];
    const float* pred_boxes   = (const float*)d_in[1];
    const float* label_maps   = (const float*)d_in[2];
    const float* boxes        = (const float*)d_in[3];
    const int*   class_labels = (const int*)d_in[4];
    float* out = (float*)d_out;

    cudaFuncSetAttribute(cost_kernel, cudaFuncAttributeMaxDynamicSharedMemorySize, DYNSMEM);

    prep_kernel<<<FEAT_BLOCKS + BTn, 256>>>(logits, label_maps, boxes, class_labels);
    cost_kernel<<<dim3(BTn / BN, MPAD / BM), 512, DYNSMEM>>>(pred_boxes, out);
}

// round 16
// speedup vs baseline: 1.2566x; 1.2566x over previous
#include <cuda_runtime.h>
#include <cuda_bf16.h>
#include <math.h>
#include <stdint.h>

// ---------------- problem constants ----------------
#define Tt   40
#define Ll   91
#define Cc   512
#define BQn  14400
#define BTn  640
#define MPAD 14464            // 113 * 128

// quantization scales (power of two: exact)
#define SA   16.0f
#define SB   512.0f
#define CLS_SCALE (2.0f / (SA * SB))

// ---------------- GEMM tiling (fp8: 1 byte/elt) ----------------
#define BM 128
#define BN 64
#define BKB 128               // K-bytes per chunk
#define NCH 4                 // 512 / 128
#define A_OFF 32768           // A pair buffers after resident B
#define A_PAIR_BYTES 8192     // 2 stages x 32 rows x 128B
#define DYNSMEM 65536         // 32KB B + 32KB A

#define FEAT_BLOCKS 3600      // BQn*Cc/8/256

// ---------------- scratch (zero-initialized device globals) ----------------
__device__ uint8_t g_A[(size_t)MPAD * Cc];   // fp8 e4m3 focal features * SA (pad rows zero)
__device__ uint8_t g_B[(size_t)BTn * Cc];    // fp8 e4m3 normalized lm * SB
__device__ float   g_tbox[BTn * 8];          // cx,cy,w,h,x0,y0,x1,y1

// ---------------- helpers ----------------
__device__ __forceinline__ uint32_t cvta_s(const void* p) {
    uint32_t a;
    asm("{ .reg .u64 t; cvta.to.shared.u64 t, %1; cvt.u32.u64 %0, t; }"
        : "=r"(a) : "l"(p));
    return a;
}

#define CP16(dst, src) asm volatile("cp.async.cg.shared.global [%0], [%1], 16;" :: "r"(dst), "l"(src))
#define CPCOMMIT()     asm volatile("cp.async.commit_group;")
#define CPWAIT(n)      asm volatile("cp.async.wait_group %0;" :: "n"(n))
#define PAIR_BAR(id)   asm volatile("bar.sync %0, 64;" :: "r"(id) : "memory")

__device__ __forceinline__ void ldsm4(uint32_t& r0, uint32_t& r1, uint32_t& r2,
                                      uint32_t& r3, uint32_t addr) {
    asm volatile("ldmatrix.sync.aligned.m8n8.x4.shared.b16 {%0,%1,%2,%3}, [%4];"
                 : "=r"(r0), "=r"(r1), "=r"(r2), "=r"(r3) : "r"(addr));
}

__device__ __forceinline__ void mma_fp8(float* d, const uint32_t* a,
                                        const uint32_t* b) {
    asm volatile(
        "mma.sync.aligned.m16n8k32.row.col.f32.e4m3.e4m3.f32 "
        "{%0,%1,%2,%3}, {%4,%5,%6,%7}, {%8,%9}, {%0,%1,%2,%3};"
        : "+f"(d[0]), "+f"(d[1]), "+f"(d[2]), "+f"(d[3])
        : "r"(a[0]), "r"(a[1]), "r"(a[2]), "r"(a[3]), "r"(b[0]), "r"(b[1]));
}

__device__ __forceinline__ uint16_t f2_to_e4m3x2(float lo, float hi) {
    uint16_t r;
    asm("cvt.rn.satfinite.e4m3x2.f32 %0, %1, %2;" : "=h"(r) : "f"(hi), "f"(lo));
    return r;
}

// swizzled byte offset: 128B rows, 8 chunks of 16B, 8-way XOR
__device__ __forceinline__ uint32_t swoff(int r, int c) {
    return (uint32_t)(r * 128 + ((c ^ (r & 7)) << 4));
}

// ---------------- focal feature: 3-MUFU softplus form ----------------
__device__ __forceinline__ float focal_feat(float x) {
    float e = __expf(-x);
    float t = __logf(1.f + e);
    float p = __fdividef(1.f, 1.f + e);
    float q = 1.f - p;
    return 0.25f * q * q * t - 0.75f * p * p * (x + t);
}

// ---------------- kernel 1: fused prep (features + targets) ----------------
__global__ void prep_kernel(const float* __restrict__ logits,
                            const float* __restrict__ label_maps,
                            const float* __restrict__ boxes,
                            const int*   __restrict__ class_labels) {
    int bid = blockIdx.x;
    int tid = threadIdx.x;
    if (bid < FEAT_BLOCKS) {
        int base = (bid * 256 + tid) * 8;
        float4 x0 = *(const float4*)(logits + base);
        float4 x1 = *(const float4*)(logits + base + 4);
        float f[8] = { x0.x, x0.y, x0.z, x0.w, x1.x, x1.y, x1.z, x1.w };
        uint16_t w[4];
        #pragma unroll
        for (int i = 0; i < 4; i++)
            w[i] = f2_to_e4m3x2(focal_feat(f[2 * i]) * SA,
                                focal_feat(f[2 * i + 1]) * SA);
        uint2 pk;
        pk.x = (uint32_t)w[0] | ((uint32_t)w[1] << 16);
        pk.y = (uint32_t)w[2] | ((uint32_t)w[3] << 16);
        *(uint2*)(g_A + base) = pk;
    } else {
        int j = bid - FEAT_BLOCKS;          // 0..639
        int b = j / Tt;
        int cls = class_labels[j];
        const float* row = label_maps + ((size_t)b * Ll + cls) * Cc;
        float2 v = *(const float2*)(row + tid * 2);
        float s = v.x + v.y;
        #pragma unroll
        for (int o = 16; o; o >>= 1) s += __shfl_xor_sync(0xffffffffu, s, o);
        __shared__ float red[8];
        if ((tid & 31) == 0) red[tid >> 5] = s;
        __syncthreads();
        float inv = SB / (red[0] + red[1] + red[2] + red[3] +
                          red[4] + red[5] + red[6] + red[7]);
        *(uint16_t*)(g_B + (size_t)j * Cc + tid * 2) =
            f2_to_e4m3x2(v.x * inv, v.y * inv);
        if (tid == 0) {
            float cx = boxes[j * 4 + 0], cy = boxes[j * 4 + 1];
            float w  = boxes[j * 4 + 2], h  = boxes[j * 4 + 3];
            float* o = g_tbox + j * 8;
            o[0] = cx; o[1] = cy; o[2] = w; o[3] = h;
            o[4] = cx - 0.5f * w; o[5] = cy - 0.5f * h;
            o[6] = cx + 0.5f * w; o[7] = cy + 0.5f * h;
        }
    }
}

// ---------------- kernel 2: fp8 GEMM, warp-pair pipelines, fused epilogue ----------------
extern __shared__ char dynsmem[];

__global__ __launch_bounds__(256, 3) void cost_kernel(
    const float* __restrict__ pred_boxes,
    float* __restrict__ outp) {

    const int tid = threadIdx.x;
    const int wid = tid >> 5;
    const int lane = tid & 31;
    const int pair = wid & 3;        // pair owns A rows [pair*32, pair*32+32)
    const int wn = wid >> 2;         // 0/1: B column half
    const int l64 = (wn << 5) | lane;
    const int m0 = blockIdx.y * BM;
    const int n0 = blockIdx.x * BN;

    uint32_t smem = cvta_s(dynsmem);
    const uint32_t a_base = smem + A_OFF + pair * A_PAIR_BYTES;
    __shared__ float s_tbox[BN * 8];     // 2KB

    // stage target boxes
    #pragma unroll
    for (int i = tid; i < BN * 2; i += 256)
        ((float4*)s_tbox)[i] = *(const float4*)(g_tbox + (size_t)n0 * 8 + i * 4);

    // ---- prologue loads ----
    // B: whole 64x512 tile as 4 chunks of 64x128B
    {
        #pragma unroll
        for (int i = 0; i < 8; i++) {
            int idx = tid + i * 256;          // 0..2047
            int ch = idx >> 9;
            int w9 = idx & 511;
            int r = w9 >> 3, c = w9 & 7;
            CP16(smem + ch * 8192 + swoff(r, c),
                 g_B + (size_t)(n0 + r) * Cc + ch * BKB + c * 16);
        }
        CPCOMMIT();
    }
    auto issueA = [&](int ch) {
        uint32_t st = a_base + (ch & 1) * 4096;
        const uint8_t* Ag = g_A + (size_t)(m0 + pair * 32) * Cc + ch * BKB;
        #pragma unroll
        for (int i = 0; i < 4; i++) {
            int idx = l64 + i * 64;
            int r = idx >> 3, c = idx & 7;
            CP16(st + swoff(r, c), Ag + (size_t)r * Cc + c * 16);
        }
        CPCOMMIT();
    };
    issueA(0); issueA(1);

    CPWAIT(2);             // B complete
    __syncthreads();       // B + tbox visible CTA-wide

    // ldmatrix constants (R8-proven)
    const int ar = lane & 15;
    const int ac = lane >> 4;
    const int axr = ar & 7;
    const int br = wn * 32 + ((lane >> 4) << 3) + (lane & 7);
    const int bc = (lane >> 3) & 1;
    const int bxr = br & 7;

    float acc[2][4][4];
    #pragma unroll
    for (int i = 0; i < 2; i++)
        #pragma unroll
        for (int j = 0; j < 4; j++)
            #pragma unroll
            for (int e = 0; e < 4; e++) acc[i][j][e] = 0.f;

    #pragma unroll
    for (int ch = 0; ch < NCH; ch++) {
        if (ch < NCH - 1) CPWAIT(1); else CPWAIT(0);
        PAIR_BAR(pair + 1);                     // pair's A(ch) visible

        uint32_t ast = a_base + (ch & 1) * 4096 + (uint32_t)ar * 128;
        uint32_t bst = smem + ch * 8192 + (uint32_t)br * 128;
        #pragma unroll
        for (int ks = 0; ks < 4; ks++) {
            uint32_t a[2][4], b[4][2];
            uint32_t ako = (uint32_t)(((ks * 2 + ac) ^ axr) << 4);
            uint32_t bko = (uint32_t)(((ks * 2 + bc) ^ bxr) << 4);
            ldsm4(a[0][0], a[0][1], a[0][2], a[0][3], ast + ako);
            ldsm4(a[1][0], a[1][1], a[1][2], a[1][3], ast + 2048 + ako);
            ldsm4(b[0][0], b[0][1], b[1][0], b[1][1], bst + bko);
            ldsm4(b[2][0], b[2][1], b[3][0], b[3][1], bst + 2048 + bko);
            #pragma unroll
            for (int mt = 0; mt < 2; mt++)
                #pragma unroll
                for (int nt = 0; nt < 4; nt++)
                    mma_fp8(acc[mt][nt], a[mt], b[nt]);
        }

        if (ch + 2 < NCH) {
            PAIR_BAR(pair + 1);                 // both warps done reading stage
            issueA(ch + 2);
        }
    }

    // ---------------- fused epilogue ----------------
    const int rbase = m0 + pair * 32 + (lane >> 2);
    const int cbase = wn * 32 + ((lane & 3) << 1);

    // hoist the 4 pred_boxes rows this thread owns (R7-proven, 80 regs)
    float4 qb[2][2];
    #pragma unroll
    for (int mt = 0; mt < 2; mt++)
        #pragma unroll
        for (int half = 0; half < 2; half++) {
            int m = rbase + mt * 16 + half * 8;
            qb[mt][half] = (m < BQn) ? *(const float4*)(pred_boxes + (size_t)m * 4)
                                     : make_float4(0.f, 0.f, 1.f, 1.f);
        }

    #pragma unroll
    for (int nt = 0; nt < 4; nt++) {
        int nl = cbase + nt * 8;
        float4 tc0 = *(const float4*)(s_tbox + nl * 8);
        float4 tk0 = *(const float4*)(s_tbox + nl * 8 + 4);
        float4 tc1 = *(const float4*)(s_tbox + (nl + 1) * 8);
        float4 tk1 = *(const float4*)(s_tbox + (nl + 1) * 8 + 4);
        float ta0 = tc0.z * tc0.w;
        float ta1 = tc1.z * tc1.w;

        #pragma unroll
        for (int mt = 0; mt < 2; mt++) {
            #pragma unroll
            for (int half = 0; half < 2; half++) {
                int m = rbase + mt * 16 + half * 8;
                if (m >= BQn) continue;
                float4 q = qb[mt][half];
                float qx0 = q.x - 0.5f * q.z, qy0 = q.y - 0.5f * q.w;
                float qx1 = q.x + 0.5f * q.z, qy1 = q.y + 0.5f * q.w;
                float qarea = q.z * q.w;

                float r2[2];
                #pragma unroll
                for (int u = 0; u < 2; u++) {
                    float4 tc = u ? tc1 : tc0;
                    float4 tk = u ? tk1 : tk0;
                    float tarea = u ? ta1 : ta0;
                    float l1 = fabsf(q.x - tc.x) + fabsf(q.y - tc.y) +
                               fabsf(q.z - tc.z) + fabsf(q.w - tc.w);
                    float ltx = fmaxf(qx0, tk.x), lty = fmaxf(qy0, tk.y);
                    float rbx = fminf(qx1, tk.z), rby = fminf(qy1, tk.w);
                    float iwu = rbx - ltx, ihu = rby - lty;     // signed widths
                    float iw = fmaxf(iwu, 0.f), ih = fmaxf(ihu, 0.f);
                    float inter = iw * ih;
                    float uni = qarea + tarea - inter;
                    // enclosing box via width identity (no extra min/max)
                    float ew = q.z + tc.z - iwu;
                    float eh = q.w + tc.w - ihu;
                    float areaE = ew * eh;
                    float num = inter * areaE - uni * areaE + uni * uni;
                    float giou = __fdividef(num, uni * areaE);
                    float cls = acc[mt][nt][half * 2 + u];
                    r2[u] = 5.0f * l1 + CLS_SCALE * cls - 2.0f * giou;
                }
                *(float2*)(outp + (size_t)m * BTn + n0 + nl) = make_float2(r2[0], r2[1]);
            }
        }
    }
}

// ---------------- launcher ----------------
extern "C" void kernel_launch(void* const* d_in, const int* in_sizes, int n_in,
                              void* d_out, int out_size) {
    const float* logits       = (const float*)d_in[0];
    const float* pred_boxes   = (const float*)d_in[1];
    const float* label_maps   = (const float*)d_in[2];
    const float* boxes        = (const float*)d_in[3];
    const int*   class_labels = (const int*)d_in[4];
    float* out = (float*)d_out;

    cudaFuncSetAttribute(cost_kernel, cudaFuncAttributeMaxDynamicSharedMemorySize, DYNSMEM);

    prep_kernel<<<FEAT_BLOCKS + BTn, 256>>>(logits, label_maps, boxes, class_labels);
    cost_kernel<<<dim3(BTn / BN, MPAD / BM), 256, DYNSMEM>>>(pred_boxes, out);
}